// round 7
// baseline (speedup 1.0000x reference)
#include <cuda_runtime.h>
#include <cuda_fp16.h>

#define BB   32      // batch
#define NN   2048    // input capsules
#define IL   32      // input capsule length
#define CC   32      // output capsules
#define LL   32      // output capsule length
#define KK   1024    // CC*LL
#define NCH1 128     // j-chunks for u/s0 kernel (16 j each)
#define PCH  32      // pass CTAs per b (each CTA covers 64 j)

typedef unsigned long long ull;

// Scratch (device globals: allocation-free rule)
__device__ __half g_uh [(size_t)BB * NN * KK];    // 128 MB prediction tensor (fp16)
__device__ float  g_s0p[(size_t)BB * NCH1 * KK];  // s partials, round 0 (16 MB)
__device__ float  g_sp [(size_t)BB * PCH * KK];   // s partials, rounds 1/2 (4 MB)
__device__ float  g_v0 [BB * KK];
__device__ float  g_v1 [BB * KK];
__device__ float  g_dummy[1];

__device__ __forceinline__ void ffma2(ull& acc, ull a, ull b) {
    asm("fma.rn.f32x2 %0, %1, %2, %0;" : "+l"(acc) : "l"(a), "l"(b));
}
__device__ __forceinline__ void fadd2(ull& acc, ull a) {
    asm("add.rn.f32x2 %0, %1, %0;" : "+l"(acc) : "l"(a));
}
__device__ __forceinline__ float2 up2(ull v) {
    float2 f;
    asm("mov.b64 {%0, %1}, %2;" : "=f"(f.x), "=f"(f.y) : "l"(v));
    return f;
}
__device__ __forceinline__ __half2 geth2(const uint4& v, int p) {
    unsigned u = (&v.x)[p];
    return *reinterpret_cast<const __half2*>(&u);
}

__global__ void k_dummy(float* p) { if (threadIdx.x == 0) p[0] = 0.f; }

// K1 v4: u[b,j,k] = sum_i x[b,j,i]*W[j,i,k]; s0 partial = sum_j u / 32.
// 512 threads: kg = tid&127 owns 2 k (one f32x2), bg = tid>>7 owns 8 b.
// Per-thread state halved vs v3 (acc 16 + s0 16 + ring-2 W 8 regs) ->
// fits 64 regs -> 2 CTAs x 512 = 1024 thr/SM = 8 warps/SMSP (2.3x round 6)
// to feed the FFMA2 pipe. W still read exactly once chip-wide.
__global__ void __launch_bounds__(512, 2)
k1(const float* __restrict__ x, const float* __restrict__ Wt) {
    const int kg    = threadIdx.x & 127;   // f32x2 index within 256-k quarter
    const int bg    = threadIdx.x >> 7;    // 0..3 -> 8 b's each
    const int chunk = blockIdx.x;          // 0..127
    const int kq    = blockIdx.y;          // 0..3, 256 k each
    __shared__ float2 xs[4][32][32];       // 32 KB x duplicated for f32x2

    ull s0[8];
#pragma unroll
    for (int bb = 0; bb < 8; bb++) s0[bb] = 0ull;

    for (int sc = 0; sc < 4; sc++) {
        const int jb = chunk * 16 + sc * 4;

        __syncthreads();                   // xs reuse guard
#pragma unroll
        for (int r = 0; r < 8; r++) {
            int idx = threadIdx.x + 512 * r;
            int jl = idx >> 10, rem = idx & 1023;
            int b = rem >> 5, i = rem & 31;
            float v = x[((size_t)b * NN + jb + jl) * IL + i];
            xs[jl][b][i] = make_float2(v, v);
        }
        __syncthreads();

        // W as ull (f32x2): index = (j*32 + i)*512 + kq*128 + kg.
        // pair p -> (j = p>>4, i = 2*(p&15)); w1 = next i (+512 ull).
        const ull* Wb = reinterpret_cast<const ull*>(Wt) +
                        (size_t)jb * 16384 + (size_t)kq * 128 + kg;
#define PADDR(p) (Wb + ((size_t)((p) >> 4) * 16384 + (size_t)((p) & 15) * 1024))

        ull rw0[2], rw1[2];                // ring-2 of W pairs
#pragma unroll
        for (int pp = 0; pp < 2; pp++) { rw0[pp] = PADDR(pp)[0]; rw1[pp] = PADDR(pp)[512]; }

        ull acc[8];
#pragma unroll
        for (int bb = 0; bb < 8; bb++) acc[bb] = 0ull;

        for (int j = 0; j < 4; j++) {
#pragma unroll
            for (int pr = 0; pr < 16; pr++) {
                const int p = j * 16 + pr;
                const int s = pr & 1;      // ring slot (16 % 2 == 0)
                ull w0 = rw0[s], w1 = rw1[s];
                if (p + 2 < 64) { rw0[s] = PADDR(p + 2)[0]; rw1[s] = PADDR(p + 2)[512]; }
                const int i = pr * 2;
#pragma unroll
                for (int bb = 0; bb < 8; bb++) {
                    ulonglong2 xx = *reinterpret_cast<const ulonglong2*>(&xs[j][bg * 8 + bb][i]);
                    ffma2(acc[bb], w0, xx.x);
                    ffma2(acc[bb], w1, xx.y);
                }
            }
            // store u row (fp16 half2), fold into s0, reset acc
            const size_t kbase = (size_t)kq * 256 + (size_t)kg * 2;
            const int jg = jb + j;
#pragma unroll
            for (int bb = 0; bb < 8; bb++) {
                const int b = bg * 8 + bb;
                float2 a = up2(acc[bb]);
                __half2 h = __floats2half2_rn(a.x, a.y);
                *reinterpret_cast<unsigned*>(g_uh + ((size_t)b * NN + jg) * KK + kbase) =
                    *reinterpret_cast<unsigned*>(&h);
                fadd2(s0[bb], acc[bb]);
                acc[bb] = 0ull;
            }
        }
#undef PADDR
    }

    const float sc = 1.0f / 32.0f;         // softmax(0) coupling = 1/C
    const size_t kbase = (size_t)kq * 256 + (size_t)kg * 2;
#pragma unroll
    for (int bb = 0; bb < 8; bb++) {
        const int b = bg * 8 + bb;
        float2 a = up2(s0[bb]);
        *reinterpret_cast<float2*>(
            g_s0p + ((size_t)b * NCH1 + chunk) * KK + kbase) =
            make_float2(a.x * sc, a.y * sc);
    }
}

// Routing pass v4 (unchanged from round 6 — measured ~28us). Lane t's uint4
// group q (index t+32q of the u row) covers k = 8t+256q+e (e<8), all in
// capsule c_q = (t>>2)+8q. Quad shfl completes each logit; shfl xor 4/8/16
// spans the 32 capsules for the softmax. v as fp16x2 registers; u raw,
// converted on the fly. Two rows per body, interleaved softmax chains.
template <int NP>
__global__ void __launch_bounds__(256, 2)
k_pass(const float* __restrict__ vin0, const float* __restrict__ vin1,
       float* __restrict__ sp) {
    const int b = blockIdx.y;
    const int w = threadIdx.x >> 5;
    const int t = threadIdx.x & 31;

    __shared__ float red[8][1032];     // CTA reduction (16B-aligned rows)

    // v as half2 registers at the u k-mapping (NP==2 folds v0+v1)
    __half2 vh[16];
#pragma unroll
    for (int q = 0; q < 4; q++) {
        float4 a = *reinterpret_cast<const float4*>(vin0 + (size_t)b * KK + 8 * t + 256 * q);
        float4 c4 = *reinterpret_cast<const float4*>(vin0 + (size_t)b * KK + 8 * t + 256 * q + 4);
        if (NP == 2) {
            float4 a1 = *reinterpret_cast<const float4*>(vin1 + (size_t)b * KK + 8 * t + 256 * q);
            float4 c1 = *reinterpret_cast<const float4*>(vin1 + (size_t)b * KK + 8 * t + 256 * q + 4);
            a.x += a1.x; a.y += a1.y; a.z += a1.z; a.w += a1.w;
            c4.x += c1.x; c4.y += c1.y; c4.z += c1.z; c4.w += c1.w;
        }
        vh[q * 4 + 0] = __floats2half2_rn(a.x, a.y);
        vh[q * 4 + 1] = __floats2half2_rn(a.z, a.w);
        vh[q * 4 + 2] = __floats2half2_rn(c4.x, c4.y);
        vh[q * 4 + 3] = __floats2half2_rn(c4.z, c4.w);
    }

    float sacc[32];
#pragma unroll
    for (int l = 0; l < 32; l++) sacc[l] = 0.f;

    const int jbase = blockIdx.x * 64 + w * 8;   // 8 warps x 8 j = 64 j / CTA
    const uint4* up = reinterpret_cast<const uint4*>(g_uh + ((size_t)b * NN + jbase) * KK);

    uint4 raw0[4], raw1[4];
#pragma unroll
    for (int q = 0; q < 4; q++) raw0[q] = up[q * 32 + t];          // j0
#pragma unroll
    for (int q = 0; q < 4; q++) raw1[q] = up[128 + q * 32 + t];    // j1

    for (int jb = 0; jb < 8; jb += 2) {
        // free raw0 early: copy, then prefetch j+2 into it
        uint4 cpy0[4];
#pragma unroll
        for (int q = 0; q < 4; q++) cpy0[q] = raw0[q];
        if (jb + 2 < 8) {
#pragma unroll
            for (int q = 0; q < 4; q++) raw0[q] = up[(jb + 2) * 128 + q * 32 + t];
        }

        // logits for both rows (HFMA2 dot), interleaved
        float d0[4], d1[4];
#pragma unroll
        for (int q = 0; q < 4; q++) {
            __half2 a0 = __float2half2_rn(0.f), a1 = __float2half2_rn(0.f);
#pragma unroll
            for (int p = 0; p < 4; p++) {
                a0 = __hfma2(geth2(cpy0[q], p), vh[q * 4 + p], a0);
                a1 = __hfma2(geth2(raw1[q], p), vh[q * 4 + p], a1);
            }
            float2 f0 = __half22float2(a0), f1 = __half22float2(a1);
            d0[q] = f0.x + f0.y;
            d1[q] = f1.x + f1.y;
            d0[q] += __shfl_xor_sync(0xffffffffu, d0[q], 1);
            d1[q] += __shfl_xor_sync(0xffffffffu, d1[q], 1);
            d0[q] += __shfl_xor_sync(0xffffffffu, d0[q], 2);
            d1[q] += __shfl_xor_sync(0xffffffffu, d1[q], 2);
        }

        // softmax over 32 capsules, two independent chains interleaved
        float m0 = fmaxf(fmaxf(d0[0], d0[1]), fmaxf(d0[2], d0[3]));
        float m1 = fmaxf(fmaxf(d1[0], d1[1]), fmaxf(d1[2], d1[3]));
        m0 = fmaxf(m0, __shfl_xor_sync(0xffffffffu, m0, 4));
        m1 = fmaxf(m1, __shfl_xor_sync(0xffffffffu, m1, 4));
        m0 = fmaxf(m0, __shfl_xor_sync(0xffffffffu, m0, 8));
        m1 = fmaxf(m1, __shfl_xor_sync(0xffffffffu, m1, 8));
        m0 = fmaxf(m0, __shfl_xor_sync(0xffffffffu, m0, 16));
        m1 = fmaxf(m1, __shfl_xor_sync(0xffffffffu, m1, 16));

        float ce0[4], ce1[4];
#pragma unroll
        for (int q = 0; q < 4; q++) {
            ce0[q] = __expf(d0[q] - m0);
            ce1[q] = __expf(d1[q] - m1);
        }
        float Z0 = (ce0[0] + ce0[1]) + (ce0[2] + ce0[3]);
        float Z1 = (ce1[0] + ce1[1]) + (ce1[2] + ce1[3]);
        Z0 += __shfl_xor_sync(0xffffffffu, Z0, 4);
        Z1 += __shfl_xor_sync(0xffffffffu, Z1, 4);
        Z0 += __shfl_xor_sync(0xffffffffu, Z0, 8);
        Z1 += __shfl_xor_sync(0xffffffffu, Z1, 8);
        Z0 += __shfl_xor_sync(0xffffffffu, Z0, 16);
        Z1 += __shfl_xor_sync(0xffffffffu, Z1, 16);
        const float i0 = __fdividef(1.0f, Z0);
        const float i1 = __fdividef(1.0f, Z1);

        // accumulate both rows (cvt on the fly)
#pragma unroll
        for (int q = 0; q < 4; q++) {
            const float c0 = ce0[q] * i0;
            const float c1 = ce1[q] * i1;
#pragma unroll
            for (int p = 0; p < 4; p++) {
                float2 f = __half22float2(geth2(cpy0[q], p));
                sacc[8 * q + 2 * p]     += c0 * f.x;
                sacc[8 * q + 2 * p + 1] += c0 * f.y;
                f = __half22float2(geth2(raw1[q], p));
                sacc[8 * q + 2 * p]     += c1 * f.x;
                sacc[8 * q + 2 * p + 1] += c1 * f.y;
            }
        }

        // raw1 now free: prefetch j+3
        if (jb + 3 < 8) {
#pragma unroll
            for (int q = 0; q < 4; q++) raw1[q] = up[(jb + 3) * 128 + q * 32 + t];
        }
    }

    // CTA reduction across the 8 warps (natural k layout)
#pragma unroll
    for (int q = 0; q < 4; q++) {
        *reinterpret_cast<float4*>(&red[w][8 * t + 256 * q])     =
            make_float4(sacc[8 * q + 0], sacc[8 * q + 1], sacc[8 * q + 2], sacc[8 * q + 3]);
        *reinterpret_cast<float4*>(&red[w][8 * t + 256 * q + 4]) =
            make_float4(sacc[8 * q + 4], sacc[8 * q + 5], sacc[8 * q + 6], sacc[8 * q + 7]);
    }
    __syncthreads();

    float4 s = make_float4(0.f, 0.f, 0.f, 0.f);
#pragma unroll
    for (int ww = 0; ww < 8; ww++) {
        float4 p = *reinterpret_cast<const float4*>(&red[ww][4 * threadIdx.x]);
        s.x += p.x; s.y += p.y; s.z += p.z; s.w += p.w;
    }
    *reinterpret_cast<float4*>(sp + ((size_t)b * PCH + blockIdx.x) * KK + 4 * threadIdx.x) = s;
}

// Finalize: reduce NCH chunk partials + biases, squash -> v.
// One CTA (8 warps) per (b,c) for memory-level parallelism on the reduction.
template <int NCH>
__global__ void __launch_bounds__(256)
k_fin(const float* __restrict__ sp, const float* __restrict__ biases,
      float* __restrict__ vout) {
    const int bc = blockIdx.x;
    const int b = bc >> 5, c = bc & 31;
    const int w = threadIdx.x >> 5, lane = threadIdx.x & 31;

    float s = 0.f;
    const float* p = sp + (size_t)b * NCH * KK + c * LL + lane;
#pragma unroll 8
    for (int n = w; n < NCH; n += 8) s += p[(size_t)n * KK];

    __shared__ float red[8][32];
    red[w][lane] = s;
    __syncthreads();

    if (w == 0) {
        float v = biases[c * LL + lane];
#pragma unroll
        for (int ww = 0; ww < 8; ww++) v += red[ww][lane];
        float n2 = v * v;
#pragma unroll
        for (int o = 16; o; o >>= 1) n2 += __shfl_xor_sync(0xffffffffu, n2, o);
        const float nn = sqrtf(n2);
        const float f = n2 / (1.0f + n2) / (nn + 1e-7f);   // squash factor
        vout[(size_t)b * KK + c * LL + lane] = f * v;
    }
}

extern "C" void kernel_launch(void* const* d_in, const int* in_sizes, int n_in,
                              void* d_out, int out_size) {
    const float* x      = (const float*)d_in[0];  // [32,8,8,32,32] = [B,N,iL]
    const float* Wt     = (const float*)d_in[1];  // [2048,32,1024]
    const float* biases = (const float*)d_in[2];  // [32,32]
    float* out = (float*)d_out;                   // [32,32,32]

    float *s0p, *sp, *v0, *v1, *dm;
    cudaGetSymbolAddress((void**)&s0p, g_s0p);
    cudaGetSymbolAddress((void**)&sp,  g_sp);
    cudaGetSymbolAddress((void**)&v0,  g_v0);
    cudaGetSymbolAddress((void**)&v1,  g_v1);
    cudaGetSymbolAddress((void**)&dm,  g_dummy);

    // 3 dummies keep k1 in the ncu-profiled slot.
    k_dummy<<<1, 32>>>(dm);                              // 0
    k_dummy<<<1, 32>>>(dm);                              // 1
    k_dummy<<<1, 32>>>(dm);                              // 2
    k1<<<dim3(NCH1, 4), 512>>>(x, Wt);                   // 3 <- profiled
    k_fin<NCH1><<<BB * CC, 256>>>(s0p, biases, v0);      // 4
    k_pass<1><<<dim3(PCH, BB), 256>>>(v0, v0, sp);       // 5
    k_fin<PCH><<<BB * CC, 256>>>(sp, biases, v1);        // 6
    k_pass<2><<<dim3(PCH, BB), 256>>>(v0, v1, sp);       // 7
    k_fin<PCH><<<BB * CC, 256>>>(sp, biases, out);       // 8
}

// round 8
// speedup vs baseline: 1.4918x; 1.4918x over previous
#include <cuda_runtime.h>
#include <cuda_fp16.h>

#define BB   32      // batch
#define NN   2048    // input capsules
#define IL   32      // input capsule length
#define CC   32      // output capsules
#define LL   32      // output capsule length
#define KK   1024    // CC*LL
#define NCH1 128     // j-chunks for u/s0 kernel (16 j each)
#define PCH  32      // pass CTAs per b (each CTA covers 64 j)

typedef unsigned long long ull;

// Scratch (device globals: allocation-free rule)
__device__ __half g_uh [(size_t)BB * NN * KK];    // 128 MB prediction tensor (fp16)
__device__ float  g_s0p[(size_t)BB * NCH1 * KK];  // s partials, round 0 (16 MB)
__device__ float  g_sp [(size_t)BB * PCH * KK];   // s partials, rounds 1/2 (4 MB)
__device__ float  g_v0 [BB * KK];
__device__ float  g_v1 [BB * KK];
__device__ float  g_dummy[1];

__device__ __forceinline__ void ffma2(ull& acc, ull a, ull b) {
    asm("fma.rn.f32x2 %0, %1, %2, %0;" : "+l"(acc) : "l"(a), "l"(b));
}
__device__ __forceinline__ void fadd2(ull& acc, ull a) {
    asm("add.rn.f32x2 %0, %1, %0;" : "+l"(acc) : "l"(a));
}
__device__ __forceinline__ float2 up2(ull v) {
    float2 f;
    asm("mov.b64 {%0, %1}, %2;" : "=f"(f.x), "=f"(f.y) : "l"(v));
    return f;
}
__device__ __forceinline__ ull splat(float v) {
    ull r;
    asm("mov.b64 %0, {%1, %1};" : "=l"(r) : "f"(v));
    return r;
}
__device__ __forceinline__ ull pack2(float a, float b) {
    ull r;
    asm("mov.b64 %0, {%1, %2};" : "=l"(r) : "f"(a), "f"(b));
    return r;
}
__device__ __forceinline__ __half2 geth2(const uint4& v, int p) {
    unsigned u = (&v.x)[p];
    return *reinterpret_cast<const __half2*>(&u);
}

__global__ void k_dummy(float* p) { if (threadIdx.x == 0) p[0] = 0.f; }

// K1 v5: u[b,j,k] = sum_i x[b,j,i]*W[j,i,k]; s0 partial = sum_j u / 32.
// CTA = (16-j chunk, 256-k quarter). Thread: kg=tid&63 owns 4 k,
// bg=tid>>6 owns 8 b (as 4 f32x2 b-pairs).
// W streamed via cp.async into a 3-stage smem ring (8 i-rows x 256 k per
// stage) -> a full ~1000-cycle stage of DRAM-latency cover with zero
// register cost (the v3/v4 register rings only covered ~100-250 cyc).
// x staged transposed (xs[i][b], padded) so b-pair f32x2 operands come
// straight from one LDS.128; W scalars are splat once per i on the alu pipe.
__global__ void __launch_bounds__(256, 2)
k1(const float* __restrict__ x, const float* __restrict__ Wt) {
    const int kg    = threadIdx.x & 63;    // 4 k each
    const int bg    = threadIdx.x >> 6;    // 4 groups x 8 b
    const int chunk = blockIdx.x;          // 0..127
    const int kq    = blockIdx.y;          // 0..3
    const int j0g   = chunk * 16;

    __shared__ __align__(16) float wbuf[3][8][256];   // 24 KB W ring
    __shared__ __align__(16) float xs[2][32][36];     // 9 KB x (transposed, padded)

    // cp.async mapping: 8 rows x 32 threads x 32 B
    const int wr = threadIdx.x >> 5;
    const int wl = threadIdx.x & 31;

    auto issue_stage = [&](int g) {
        const int jg = j0g + (g >> 2);
        const int ibase = (g & 3) * 8;
        const float* src = Wt + (size_t)jg * (IL * KK) + (size_t)(ibase + wr) * KK
                         + kq * 256 + wl * 8;
        unsigned dst = (unsigned)__cvta_generic_to_shared(&wbuf[g % 3][wr][wl * 8]);
        asm volatile(
            "cp.async.cg.shared.global [%0], [%1], 16;\n\t"
            "cp.async.cg.shared.global [%2], [%3], 16;"
            :: "r"(dst), "l"(src), "r"(dst + 16), "l"(src + 4) : "memory");
    };

    ull acc[4][4], s0[4][4];               // [k][b-pair] f32x2
#pragma unroll
    for (int k = 0; k < 4; k++)
#pragma unroll
        for (int bp = 0; bp < 4; bp++) { acc[k][bp] = 0ull; s0[k][bp] = 0ull; }

    issue_stage(0);
    asm volatile("cp.async.commit_group;" ::: "memory");
    issue_stage(1);
    asm volatile("cp.async.commit_group;" ::: "memory");

    for (int g = 0; g < 64; g++) {         // 64 stages: 16 j x 4 i-blocks of 8
        asm volatile("cp.async.wait_group 1;" ::: "memory");
        __syncthreads();

        if ((g & 7) == 0) {
            // stage x for j-pair (transposed, pad 36 for aligned LDS.128)
            const int jp = j0g + (g >> 2);
#pragma unroll
            for (int r = 0; r < 8; r++) {
                int idx = threadIdx.x + 256 * r;
                int jl = idx >> 10, rem = idx & 1023;
                int b = rem >> 5, i = rem & 31;
                xs[jl][i][b] = x[((size_t)b * NN + jp + jl) * IL + i];
            }
            __syncthreads();
        }

        // compute stage g (8 i-rows)
        const int jl = (g >> 2) & 1;
        const int ib = (g & 3) * 8;
        const float (*wb)[256] = wbuf[g % 3];
#pragma unroll
        for (int ii = 0; ii < 8; ii++) {
            float4 w = *reinterpret_cast<const float4*>(&wb[ii][kg * 4]);
            ull ws0 = splat(w.x), ws1 = splat(w.y), ws2 = splat(w.z), ws3 = splat(w.w);
            float4 xa = *reinterpret_cast<const float4*>(&xs[jl][ib + ii][bg * 8]);
            float4 xb = *reinterpret_cast<const float4*>(&xs[jl][ib + ii][bg * 8 + 4]);
            ull xp0 = pack2(xa.x, xa.y), xp1 = pack2(xa.z, xa.w);
            ull xp2 = pack2(xb.x, xb.y), xp3 = pack2(xb.z, xb.w);
            ffma2(acc[0][0], ws0, xp0); ffma2(acc[0][1], ws0, xp1);
            ffma2(acc[0][2], ws0, xp2); ffma2(acc[0][3], ws0, xp3);
            ffma2(acc[1][0], ws1, xp0); ffma2(acc[1][1], ws1, xp1);
            ffma2(acc[1][2], ws1, xp2); ffma2(acc[1][3], ws1, xp3);
            ffma2(acc[2][0], ws2, xp0); ffma2(acc[2][1], ws2, xp1);
            ffma2(acc[2][2], ws2, xp2); ffma2(acc[2][3], ws2, xp3);
            ffma2(acc[3][0], ws3, xp0); ffma2(acc[3][1], ws3, xp1);
            ffma2(acc[3][2], ws3, xp2); ffma2(acc[3][3], ws3, xp3);
        }

        if ((g & 3) == 3) {
            // j complete: store u row (fp16), fold s0, reset acc
            const int jg = j0g + (g >> 2);
            const size_t kb = (size_t)kq * 256 + (size_t)kg * 4;
#pragma unroll
            for (int bp = 0; bp < 4; bp++) {
                float2 f0 = up2(acc[0][bp]), f1 = up2(acc[1][bp]);
                float2 f2 = up2(acc[2][bp]), f3 = up2(acc[3][bp]);
                const int be = bg * 8 + bp * 2;
                __half2 h0 = __floats2half2_rn(f0.x, f1.x);
                __half2 h1 = __floats2half2_rn(f2.x, f3.x);
                uint2 pk;
                pk.x = *reinterpret_cast<unsigned*>(&h0);
                pk.y = *reinterpret_cast<unsigned*>(&h1);
                *reinterpret_cast<uint2*>(g_uh + ((size_t)be * NN + jg) * KK + kb) = pk;
                h0 = __floats2half2_rn(f0.y, f1.y);
                h1 = __floats2half2_rn(f2.y, f3.y);
                pk.x = *reinterpret_cast<unsigned*>(&h0);
                pk.y = *reinterpret_cast<unsigned*>(&h1);
                *reinterpret_cast<uint2*>(g_uh + ((size_t)(be + 1) * NN + jg) * KK + kb) = pk;
#pragma unroll
                for (int k = 0; k < 4; k++) {
                    fadd2(s0[k][bp], acc[k][bp]);
                    acc[k][bp] = 0ull;
                }
            }
        }

        if (g + 2 < 64) issue_stage(g + 2);
        asm volatile("cp.async.commit_group;" ::: "memory");
    }

    // s0 partial store (softmax(0) coupling = 1/32)
    const float scl = 1.0f / 32.0f;
    const size_t kb = (size_t)kq * 256 + (size_t)kg * 4;
#pragma unroll
    for (int bp = 0; bp < 4; bp++) {
        float2 f0 = up2(s0[0][bp]), f1 = up2(s0[1][bp]);
        float2 f2 = up2(s0[2][bp]), f3 = up2(s0[3][bp]);
        const int be = bg * 8 + bp * 2;
        *reinterpret_cast<float4*>(g_s0p + ((size_t)be * NCH1 + chunk) * KK + kb) =
            make_float4(f0.x * scl, f1.x * scl, f2.x * scl, f3.x * scl);
        *reinterpret_cast<float4*>(g_s0p + ((size_t)(be + 1) * NCH1 + chunk) * KK + kb) =
            make_float4(f0.y * scl, f1.y * scl, f2.y * scl, f3.y * scl);
    }
}

// Routing pass v4 (measured ~28us each). Lane t's uint4 group q (index
// t+32q of the u row) covers k = 8t+256q+e (e<8), all in capsule
// c_q = (t>>2)+8q. Quad shfl completes each logit; shfl xor 4/8/16 spans
// the 32 capsules for the softmax. v as fp16x2 registers; u raw, converted
// on the fly. Two rows per body, interleaved softmax chains.
template <int NP>
__global__ void __launch_bounds__(256, 2)
k_pass(const float* __restrict__ vin0, const float* __restrict__ vin1,
       float* __restrict__ sp) {
    const int b = blockIdx.y;
    const int w = threadIdx.x >> 5;
    const int t = threadIdx.x & 31;

    __shared__ float red[8][1032];     // CTA reduction (16B-aligned rows)

    // v as half2 registers at the u k-mapping (NP==2 folds v0+v1)
    __half2 vh[16];
#pragma unroll
    for (int q = 0; q < 4; q++) {
        float4 a = *reinterpret_cast<const float4*>(vin0 + (size_t)b * KK + 8 * t + 256 * q);
        float4 c4 = *reinterpret_cast<const float4*>(vin0 + (size_t)b * KK + 8 * t + 256 * q + 4);
        if (NP == 2) {
            float4 a1 = *reinterpret_cast<const float4*>(vin1 + (size_t)b * KK + 8 * t + 256 * q);
            float4 c1 = *reinterpret_cast<const float4*>(vin1 + (size_t)b * KK + 8 * t + 256 * q + 4);
            a.x += a1.x; a.y += a1.y; a.z += a1.z; a.w += a1.w;
            c4.x += c1.x; c4.y += c1.y; c4.z += c1.z; c4.w += c1.w;
        }
        vh[q * 4 + 0] = __floats2half2_rn(a.x, a.y);
        vh[q * 4 + 1] = __floats2half2_rn(a.z, a.w);
        vh[q * 4 + 2] = __floats2half2_rn(c4.x, c4.y);
        vh[q * 4 + 3] = __floats2half2_rn(c4.z, c4.w);
    }

    float sacc[32];
#pragma unroll
    for (int l = 0; l < 32; l++) sacc[l] = 0.f;

    const int jbase = blockIdx.x * 64 + w * 8;   // 8 warps x 8 j = 64 j / CTA
    const uint4* up = reinterpret_cast<const uint4*>(g_uh + ((size_t)b * NN + jbase) * KK);

    uint4 raw0[4], raw1[4];
#pragma unroll
    for (int q = 0; q < 4; q++) raw0[q] = up[q * 32 + t];          // j0
#pragma unroll
    for (int q = 0; q < 4; q++) raw1[q] = up[128 + q * 32 + t];    // j1

    for (int jb = 0; jb < 8; jb += 2) {
        // free raw0 early: copy, then prefetch j+2 into it
        uint4 cpy0[4];
#pragma unroll
        for (int q = 0; q < 4; q++) cpy0[q] = raw0[q];
        if (jb + 2 < 8) {
#pragma unroll
            for (int q = 0; q < 4; q++) raw0[q] = up[(jb + 2) * 128 + q * 32 + t];
        }

        // logits for both rows (HFMA2 dot), interleaved
        float d0[4], d1[4];
#pragma unroll
        for (int q = 0; q < 4; q++) {
            __half2 a0 = __float2half2_rn(0.f), a1 = __float2half2_rn(0.f);
#pragma unroll
            for (int p = 0; p < 4; p++) {
                a0 = __hfma2(geth2(cpy0[q], p), vh[q * 4 + p], a0);
                a1 = __hfma2(geth2(raw1[q], p), vh[q * 4 + p], a1);
            }
            float2 f0 = __half22float2(a0), f1 = __half22float2(a1);
            d0[q] = f0.x + f0.y;
            d1[q] = f1.x + f1.y;
            d0[q] += __shfl_xor_sync(0xffffffffu, d0[q], 1);
            d1[q] += __shfl_xor_sync(0xffffffffu, d1[q], 1);
            d0[q] += __shfl_xor_sync(0xffffffffu, d0[q], 2);
            d1[q] += __shfl_xor_sync(0xffffffffu, d1[q], 2);
        }

        // softmax over 32 capsules, two independent chains interleaved
        float m0 = fmaxf(fmaxf(d0[0], d0[1]), fmaxf(d0[2], d0[3]));
        float m1 = fmaxf(fmaxf(d1[0], d1[1]), fmaxf(d1[2], d1[3]));
        m0 = fmaxf(m0, __shfl_xor_sync(0xffffffffu, m0, 4));
        m1 = fmaxf(m1, __shfl_xor_sync(0xffffffffu, m1, 4));
        m0 = fmaxf(m0, __shfl_xor_sync(0xffffffffu, m0, 8));
        m1 = fmaxf(m1, __shfl_xor_sync(0xffffffffu, m1, 8));
        m0 = fmaxf(m0, __shfl_xor_sync(0xffffffffu, m0, 16));
        m1 = fmaxf(m1, __shfl_xor_sync(0xffffffffu, m1, 16));

        float ce0[4], ce1[4];
#pragma unroll
        for (int q = 0; q < 4; q++) {
            ce0[q] = __expf(d0[q] - m0);
            ce1[q] = __expf(d1[q] - m1);
        }
        float Z0 = (ce0[0] + ce0[1]) + (ce0[2] + ce0[3]);
        float Z1 = (ce1[0] + ce1[1]) + (ce1[2] + ce1[3]);
        Z0 += __shfl_xor_sync(0xffffffffu, Z0, 4);
        Z1 += __shfl_xor_sync(0xffffffffu, Z1, 4);
        Z0 += __shfl_xor_sync(0xffffffffu, Z0, 8);
        Z1 += __shfl_xor_sync(0xffffffffu, Z1, 8);
        Z0 += __shfl_xor_sync(0xffffffffu, Z0, 16);
        Z1 += __shfl_xor_sync(0xffffffffu, Z1, 16);
        const float i0 = __fdividef(1.0f, Z0);
        const float i1 = __fdividef(1.0f, Z1);

        // accumulate both rows (cvt on the fly)
#pragma unroll
        for (int q = 0; q < 4; q++) {
            const float c0 = ce0[q] * i0;
            const float c1 = ce1[q] * i1;
#pragma unroll
            for (int p = 0; p < 4; p++) {
                float2 f = __half22float2(geth2(cpy0[q], p));
                sacc[8 * q + 2 * p]     += c0 * f.x;
                sacc[8 * q + 2 * p + 1] += c0 * f.y;
                f = __half22float2(geth2(raw1[q], p));
                sacc[8 * q + 2 * p]     += c1 * f.x;
                sacc[8 * q + 2 * p + 1] += c1 * f.y;
            }
        }

        // raw1 now free: prefetch j+3
        if (jb + 3 < 8) {
#pragma unroll
            for (int q = 0; q < 4; q++) raw1[q] = up[(jb + 3) * 128 + q * 32 + t];
        }
    }

    // CTA reduction across the 8 warps (natural k layout)
#pragma unroll
    for (int q = 0; q < 4; q++) {
        *reinterpret_cast<float4*>(&red[w][8 * t + 256 * q])     =
            make_float4(sacc[8 * q + 0], sacc[8 * q + 1], sacc[8 * q + 2], sacc[8 * q + 3]);
        *reinterpret_cast<float4*>(&red[w][8 * t + 256 * q + 4]) =
            make_float4(sacc[8 * q + 4], sacc[8 * q + 5], sacc[8 * q + 6], sacc[8 * q + 7]);
    }
    __syncthreads();

    float4 s = make_float4(0.f, 0.f, 0.f, 0.f);
#pragma unroll
    for (int ww = 0; ww < 8; ww++) {
        float4 p = *reinterpret_cast<const float4*>(&red[ww][4 * threadIdx.x]);
        s.x += p.x; s.y += p.y; s.z += p.z; s.w += p.w;
    }
    *reinterpret_cast<float4*>(sp + ((size_t)b * PCH + blockIdx.x) * KK + 4 * threadIdx.x) = s;
}

// Finalize: reduce NCH chunk partials + biases, squash -> v.
// One CTA (8 warps) per (b,c) for memory-level parallelism on the reduction.
template <int NCH>
__global__ void __launch_bounds__(256)
k_fin(const float* __restrict__ sp, const float* __restrict__ biases,
      float* __restrict__ vout) {
    const int bc = blockIdx.x;
    const int b = bc >> 5, c = bc & 31;
    const int w = threadIdx.x >> 5, lane = threadIdx.x & 31;

    float s = 0.f;
    const float* p = sp + (size_t)b * NCH * KK + c * LL + lane;
#pragma unroll 8
    for (int n = w; n < NCH; n += 8) s += p[(size_t)n * KK];

    __shared__ float red[8][32];
    red[w][lane] = s;
    __syncthreads();

    if (w == 0) {
        float v = biases[c * LL + lane];
#pragma unroll
        for (int ww = 0; ww < 8; ww++) v += red[ww][lane];
        float n2 = v * v;
#pragma unroll
        for (int o = 16; o; o >>= 1) n2 += __shfl_xor_sync(0xffffffffu, n2, o);
        const float nn = sqrtf(n2);
        const float f = n2 / (1.0f + n2) / (nn + 1e-7f);   // squash factor
        vout[(size_t)b * KK + c * LL + lane] = f * v;
    }
}

extern "C" void kernel_launch(void* const* d_in, const int* in_sizes, int n_in,
                              void* d_out, int out_size) {
    const float* x      = (const float*)d_in[0];  // [32,8,8,32,32] = [B,N,iL]
    const float* Wt     = (const float*)d_in[1];  // [2048,32,1024]
    const float* biases = (const float*)d_in[2];  // [32,32]
    float* out = (float*)d_out;                   // [32,32,32]

    float *s0p, *sp, *v0, *v1, *dm;
    cudaGetSymbolAddress((void**)&s0p, g_s0p);
    cudaGetSymbolAddress((void**)&sp,  g_sp);
    cudaGetSymbolAddress((void**)&v0,  g_v0);
    cudaGetSymbolAddress((void**)&v1,  g_v1);
    cudaGetSymbolAddress((void**)&dm,  g_dummy);

    // 3 dummies keep k1 in the ncu-profiled slot.
    k_dummy<<<1, 32>>>(dm);                              // 0
    k_dummy<<<1, 32>>>(dm);                              // 1
    k_dummy<<<1, 32>>>(dm);                              // 2
    k1<<<dim3(NCH1, 4), 256>>>(x, Wt);                   // 3 <- profiled
    k_fin<NCH1><<<BB * CC, 256>>>(s0p, biases, v0);      // 4
    k_pass<1><<<dim3(PCH, BB), 256>>>(v0, v0, sp);       // 5
    k_fin<PCH><<<BB * CC, 256>>>(sp, biases, v1);        // 6
    k_pass<2><<<dim3(PCH, BB), 256>>>(v0, v1, sp);       // 7
    k_fin<PCH><<<BB * CC, 256>>>(sp, biases, out);       // 8
}